// round 3
// baseline (speedup 1.0000x reference)
#include <cuda_runtime.h>

// CCC loss: B=512 rows, T=65536 cols, fp32.
// Single fused kernel, 4 chunks per row (2048 CTAs x 256 threads) to kill
// wave-quantization imbalance (512 CTAs / 148 SMs = 3.46 -> 13% tail).
// Last-arriving CTA reduces chunk partials and writes the scalar loss.

#define B 512
#define T 65536
#define CHUNKS 4
#define THREADS 256
#define GRID (B * CHUNKS)
#define CHUNK_F4 (T / CHUNKS / 4)   // 4096 float4 per chunk
#define EPS 1e-8f

__device__ float g_partials[GRID * 5];   // [row*CHUNKS+chunk][5]
__device__ unsigned int g_count;          // zero-init; reset by last block

__device__ __forceinline__ float warp_sum(float v) {
    #pragma unroll
    for (int o = 16; o > 0; o >>= 1)
        v += __shfl_down_sync(0xFFFFFFFFu, v, o);
    return v;
}

__global__ __launch_bounds__(THREADS)
void ccc_fused(const float* __restrict__ preds,
               const float* __restrict__ labels,
               float* __restrict__ out) {
    const int bx    = blockIdx.x;
    const int row   = bx >> 2;          // bx / CHUNKS
    const int chunk = bx & (CHUNKS - 1);
    const int tid   = threadIdx.x;
    const int lane  = tid & 31;
    const int wid   = tid >> 5;

    const size_t base = (size_t)row * T + (size_t)chunk * (T / CHUNKS);
    const float4* px = reinterpret_cast<const float4*>(preds  + base);
    const float4* py = reinterpret_cast<const float4*>(labels + base);

    float sx = 0.f, sy = 0.f, sxx = 0.f, syy = 0.f, sxy = 0.f;

    // 4096 float4 per chunk, 256 threads -> 16 iters/thread
    #pragma unroll 8
    for (int i = tid; i < CHUNK_F4; i += THREADS) {
        float4 x = px[i];
        float4 y = py[i];
        sx  += x.x + x.y + x.z + x.w;
        sy  += y.x + y.y + y.z + y.w;
        sxx += x.x * x.x + x.y * x.y + x.z * x.z + x.w * x.w;
        syy += y.x * y.x + y.y * y.y + y.z * y.z + y.w * y.w;
        sxy += x.x * y.x + x.y * y.y + x.z * y.z + x.w * y.w;
    }

    sx  = warp_sum(sx);
    sy  = warp_sum(sy);
    sxx = warp_sum(sxx);
    syy = warp_sum(syy);
    sxy = warp_sum(sxy);

    __shared__ float s[5][THREADS / 32];
    if (lane == 0) {
        s[0][wid] = sx;  s[1][wid] = sy;  s[2][wid] = sxx;
        s[3][wid] = syy; s[4][wid] = sxy;
    }
    __syncthreads();

    if (wid == 0) {
        const unsigned nW = THREADS / 32;  // 8
        float v0 = (lane < nW) ? s[0][lane] : 0.f;
        float v1 = (lane < nW) ? s[1][lane] : 0.f;
        float v2 = (lane < nW) ? s[2][lane] : 0.f;
        float v3 = (lane < nW) ? s[3][lane] : 0.f;
        float v4 = (lane < nW) ? s[4][lane] : 0.f;
        v0 = warp_sum(v0); v1 = warp_sum(v1); v2 = warp_sum(v2);
        v3 = warp_sum(v3); v4 = warp_sum(v4);
        if (lane == 0) {
            g_partials[bx * 5 + 0] = v0;
            g_partials[bx * 5 + 1] = v1;
            g_partials[bx * 5 + 2] = v2;
            g_partials[bx * 5 + 3] = v3;
            g_partials[bx * 5 + 4] = v4;
        }
    }

    // ---- last-block finalize ----
    __shared__ bool isLast;
    if (tid == 0) {
        __threadfence();
        unsigned c = atomicAdd(&g_count, 1u);
        isLast = (c == (unsigned)GRID - 1u);
    }
    __syncthreads();

    if (isLast) {
        const float invT = 1.0f / (float)T;
        float loss2 = 0.f;
        // 256 threads, each handles rows tid and tid+256
        #pragma unroll
        for (int r = tid; r < B; r += THREADS) {
            float fsx = 0.f, fsy = 0.f, fsxx = 0.f, fsyy = 0.f, fsxy = 0.f;
            #pragma unroll
            for (int c = 0; c < CHUNKS; c++) {
                const float* p = &g_partials[(r * CHUNKS + c) * 5];
                fsx  += p[0];
                fsy  += p[1];
                fsxx += p[2];
                fsyy += p[3];
                fsxy += p[4];
            }
            float mx = fsx * invT;
            float my = fsy * invT;
            float var_x = fsxx * invT - mx * mx;
            float var_y = fsyy * invT - my * my;
            float cov   = fsxy * invT - mx * my;
            float dm = mx - my;
            loss2 += 1.0f - 2.0f * cov / (var_x + var_y + dm * dm + EPS);
        }

        loss2 = warp_sum(loss2);
        __shared__ float sf[THREADS / 32];
        if (lane == 0) sf[wid] = loss2;
        __syncthreads();
        if (wid == 0) {
            float v = (lane < THREADS / 32) ? sf[lane] : 0.f;
            v = warp_sum(v);
            if (lane == 0) {
                out[0] = v / (float)B;
                g_count = 0;  // reset for next graph replay
            }
        }
    }
}

extern "C" void kernel_launch(void* const* d_in, const int* in_sizes, int n_in,
                              void* d_out, int out_size) {
    const float* preds  = (const float*)d_in[0];
    const float* labels = (const float*)d_in[1];
    float* out = (float*)d_out;

    ccc_fused<<<GRID, THREADS>>>(preds, labels, out);
}